// round 1
// baseline (speedup 1.0000x reference)
#include <cuda_runtime.h>
#include <cuda_bf16.h>

#define T_SEQ 4096
#define E_DIM 256
#define H_DIM 10
#define O_DIM 50257

// Scratch (device globals — no allocation allowed)
__device__ float g_xg[T_SEQ * 40];   // per-step input gate preactivations
__device__ float g_hs[T_SEQ * 10];   // hidden states

__device__ __forceinline__ float fast_tanh(float x) {
    float y;
    asm("tanh.approx.f32 %0, %1;" : "=f"(y) : "f"(x));
    return y;
}
__device__ __forceinline__ float fast_sigmoid(float x) {
    return 0.5f * fast_tanh(0.5f * x) + 0.5f;
}

// ---------------------------------------------------------------------------
// Kernel 1: xg[t][r] = emb[x[t]] . w_ih[r] + b_ih[r] + b_hh[r]
// One thread per (t, r) pair. E=256 -> 64 float4 MACs.
// ---------------------------------------------------------------------------
__global__ void embed_xg_kernel(const int* __restrict__ x,
                                const float* __restrict__ emb,
                                const float* __restrict__ w_ih,
                                const float* __restrict__ b_ih,
                                const float* __restrict__ b_hh) {
    int idx = blockIdx.x * blockDim.x + threadIdx.x;
    if (idx >= T_SEQ * 40) return;
    int t = idx / 40;
    int r = idx % 40;

    const float4* e = (const float4*)(emb + (size_t)x[t] * E_DIM);
    const float4* w = (const float4*)(w_ih + (size_t)r * E_DIM);

    float a0 = 0.f, a1 = 0.f, a2 = 0.f, a3 = 0.f;
#pragma unroll 8
    for (int q = 0; q < E_DIM / 4; q++) {
        float4 ev = __ldg(e + q);
        float4 wv = __ldg(w + q);
        a0 += ev.x * wv.x;
        a1 += ev.y * wv.y;
        a2 += ev.z * wv.z;
        a3 += ev.w * wv.w;
    }
    g_xg[idx] = (b_ih[r] + b_hh[r]) + ((a0 + a1) + (a2 + a3));
}

// ---------------------------------------------------------------------------
// Kernel 2: sequential LSTM recurrence. 1 block, 1 warp.
// Lane j (j<10) owns hidden unit j: computes gates i_j, f_j, g_j, o_j.
// w_hh rows held in registers; h broadcast via shfl each step.
// xg loads software-pipelined 8 steps ahead (off the critical chain).
// ---------------------------------------------------------------------------
__global__ void lstm_rec_kernel(const float* __restrict__ w_hh) {
    const int lane = threadIdx.x;
    const int j = (lane < H_DIM) ? lane : 0;   // lanes >=10 shadow lane 0 (harmless)

    float wi[H_DIM], wf[H_DIM], wg[H_DIM], wo[H_DIM];
#pragma unroll
    for (int k = 0; k < H_DIM; k++) {
        wi[k] = w_hh[(0 * H_DIM + j) * H_DIM + k];
        wf[k] = w_hh[(1 * H_DIM + j) * H_DIM + k];
        wg[k] = w_hh[(2 * H_DIM + j) * H_DIM + k];
        wo[k] = w_hh[(3 * H_DIM + j) * H_DIM + k];
    }

    float h = 0.f, c = 0.f;

    // Prefetch buffer: 8 steps ahead
    float buf[8][4];
#pragma unroll
    for (int s = 0; s < 8; s++) {
        buf[s][0] = g_xg[s * 40 + 0 * H_DIM + j];
        buf[s][1] = g_xg[s * 40 + 1 * H_DIM + j];
        buf[s][2] = g_xg[s * 40 + 2 * H_DIM + j];
        buf[s][3] = g_xg[s * 40 + 3 * H_DIM + j];
    }

    for (int t0 = 0; t0 < T_SEQ; t0 += 8) {
#pragma unroll
        for (int s = 0; s < 8; s++) {
            const int t = t0 + s;
            float gi = buf[s][0];
            float gf = buf[s][1];
            float gg = buf[s][2];
            float go = buf[s][3];

            // Issue next prefetch immediately (latency hidden over 8 steps)
            const int tn = t + 8;
            if (tn < T_SEQ) {
                buf[s][0] = g_xg[tn * 40 + 0 * H_DIM + j];
                buf[s][1] = g_xg[tn * 40 + 1 * H_DIM + j];
                buf[s][2] = g_xg[tn * 40 + 2 * H_DIM + j];
                buf[s][3] = g_xg[tn * 40 + 3 * H_DIM + j];
            }

            // Broadcast hidden state from lanes 0..9
            float hk[H_DIM];
#pragma unroll
            for (int k = 0; k < H_DIM; k++)
                hk[k] = __shfl_sync(0xffffffffu, h, k);

            // Split accumulators to shorten FMA dependency chains
            float ia = gi, ib = 0.f, fa = gf, fb = 0.f;
            float ga = gg, gb = 0.f, oa = go, ob = 0.f;
#pragma unroll
            for (int k = 0; k < 5; k++) {
                ia += wi[k] * hk[k];  ib += wi[k + 5] * hk[k + 5];
                fa += wf[k] * hk[k];  fb += wf[k + 5] * hk[k + 5];
                ga += wg[k] * hk[k];  gb += wg[k + 5] * hk[k + 5];
                oa += wo[k] * hk[k];  ob += wo[k + 5] * hk[k + 5];
            }
            float vi = fast_sigmoid(ia + ib);
            float vf = fast_sigmoid(fa + fb);
            float vg = fast_tanh(ga + gb);
            float vo = fast_sigmoid(oa + ob);

            c = vf * c + vi * vg;
            h = vo * fast_tanh(c);

            if (lane < H_DIM) g_hs[t * H_DIM + lane] = h;
        }
    }
}

// ---------------------------------------------------------------------------
// Kernel 3: logits[t][o] = hs[t] . W_out[o] + b_out[o]
// Pure store-bound (823 MB out). Each thread owns 4 consecutive o's
// (W rows in registers), loops over a 128-step t-chunk staged in smem.
// grid.x tiles O, grid.y tiles T.
// ---------------------------------------------------------------------------
#define TB 128
__global__ void out_gemm_kernel(const float* __restrict__ W_out,
                                const float* __restrict__ b_out,
                                float* __restrict__ out) {
    const int tid = threadIdx.x;
    const int obase = (blockIdx.x * blockDim.x + tid) * 4;
    const int tb = blockIdx.y * TB;

    float w[4][H_DIM];
    float bb[4];
#pragma unroll
    for (int r = 0; r < 4; r++) {
        const int o = obase + r;
        if (o < O_DIM) {
            bb[r] = __ldg(b_out + o);
#pragma unroll
            for (int k = 0; k < H_DIM; k++) w[r][k] = __ldg(W_out + (size_t)o * H_DIM + k);
        } else {
            bb[r] = 0.f;
#pragma unroll
            for (int k = 0; k < H_DIM; k++) w[r][k] = 0.f;
        }
    }

    __shared__ float sh[TB * H_DIM];
    for (int i = tid; i < TB * H_DIM; i += blockDim.x)
        sh[i] = g_hs[tb * H_DIM + i];
    __syncthreads();

    for (int tt = 0; tt < TB; tt++) {
        const float* hv = &sh[tt * H_DIM];
        float h0 = hv[0], h1 = hv[1], h2 = hv[2], h3 = hv[3], h4 = hv[4];
        float h5 = hv[5], h6 = hv[6], h7 = hv[7], h8 = hv[8], h9 = hv[9];
        const size_t rowbase = (size_t)(tb + tt) * O_DIM;
#pragma unroll
        for (int r = 0; r < 4; r++) {
            const int o = obase + r;
            if (o < O_DIM) {
                float acc = bb[r];
                acc += w[r][0] * h0 + w[r][1] * h1;
                acc += w[r][2] * h2 + w[r][3] * h3;
                acc += w[r][4] * h4 + w[r][5] * h5;
                acc += w[r][6] * h6 + w[r][7] * h7;
                acc += w[r][8] * h8 + w[r][9] * h9;
                out[rowbase + o] = acc;
            }
        }
    }
}

extern "C" void kernel_launch(void* const* d_in, const int* in_sizes, int n_in,
                              void* d_out, int out_size) {
    const int*   x     = (const int*)d_in[0];
    const float* emb   = (const float*)d_in[1];
    const float* w_ih  = (const float*)d_in[2];
    const float* w_hh  = (const float*)d_in[3];
    const float* b_ih  = (const float*)d_in[4];
    const float* b_hh  = (const float*)d_in[5];
    const float* W_out = (const float*)d_in[6];
    const float* b_out = (const float*)d_in[7];
    float* out = (float*)d_out;

    embed_xg_kernel<<<(T_SEQ * 40 + 255) / 256, 256>>>(x, emb, w_ih, b_ih, b_hh);
    lstm_rec_kernel<<<1, 32>>>(w_hh);
    dim3 g3((O_DIM + 256 * 4 - 1) / (256 * 4), T_SEQ / TB);
    out_gemm_kernel<<<g3, 256>>>(W_out, b_out, out);
}

// round 2
// speedup vs baseline: 1.1250x; 1.1250x over previous
#include <cuda_runtime.h>
#include <cstdint>

#define T_SEQ 4096
#define E_DIM 256
#define O_DIM 50257
#define NCHUNK 128           // 128 chunks of 32 timesteps
#define CH 32
#define GT 64                // gemm t-tile
#define GO 128               // gemm o-tile (per warp: 4 o's x 32 lanes)
#define N_OT ((O_DIM + GO - 1) / GO)   // 393
#define N_TT (T_SEQ / GT)              // 64
#define NBLK 148
#define NTHR 512
#define PF 4                 // recurrence prefetch distance

// ---------------- device globals (no allocation allowed) --------------------
__device__ float4 g_xg4[T_SEQ * 10];      // [t][j] -> (xi,xf,xg,xo), i/f/o pre-scaled by 0.5
__device__ float  g_h2[T_SEQ * 10];       // h2 = 2*h
__device__ float2 g_wpk[200];             // packed w_hh: [j][gate][pair], scaled
__device__ volatile int g_flag[NCHUNK];   // embed chunk ready flags
__device__ volatile int g_prog;           // recurrence progress (timesteps done)
__device__ int g_ticket;                  // gemm work ticket

// ---------------- helpers ---------------------------------------------------
__device__ __forceinline__ float fast_tanh(float x) {
    float y;
    asm("tanh.approx.f32 %0, %1;" : "=f"(y) : "f"(x));
    return y;
}
#define MUL2(d, a, b) asm("mul.rn.f32x2 %0, %1, %2;" : "=l"(d) : "l"(a), "l"(b))
#define FMA2(d, a, b, c) asm("fma.rn.f32x2 %0, %1, %2, %3;" : "=l"(d) : "l"(a), "l"(b), "l"(c))
#define PK2(d, lo, hi) asm("mov.b64 %0, {%1, %2};" : "=l"(d) : "f"(lo), "f"(hi))
#define UPK2(lo, hi, s) asm("mov.b64 {%0, %1}, %2;" : "=f"(lo), "=f"(hi) : "l"(s))

// ---------------- init/prep kernel ------------------------------------------
__global__ void init_kernel(const float* __restrict__ w_hh) {
    int i = threadIdx.x;
    if (i < NCHUNK) g_flag[i] = 0;
    if (i == 0) { g_prog = 0; g_ticket = 0; }
    if (i < 200) {
        // layout: idx = j*20 + gate*5 + p
        int j = i / 20;
        int gate = (i / 5) % 4;
        int p = i % 5;
        // sigmoid half-angle fold (0.5 for i,f,o) x h2=2h fold (0.5 for all)
        float s = (gate == 2) ? 0.5f : 0.25f;
        int r = gate * 10 + j;
        g_wpk[i] = make_float2(w_hh[r * 10 + 2 * p] * s,
                               w_hh[r * 10 + 2 * p + 1] * s);
    }
}

// ---------------- recurrence (one warp, block NBLK-1) -----------------------
__device__ __forceinline__ void wait_flag(int k) {
    while (g_flag[k] == 0) __nanosleep(64);
    __threadfence();
}

__device__ void recurrence_warp() {
    const int lane = threadIdx.x;
    const int j = (lane < 10) ? lane : 0;

    // packed, pre-scaled recurrent weights (5 f32x2 per gate)
    const unsigned long long* wpu =
        (const unsigned long long*)(g_wpk) + (size_t)j * 20;
    unsigned long long wi[5], wf[5], wg[5], wo[5];
#pragma unroll
    for (int p = 0; p < 5; p++) {
        wi[p] = wpu[p];
        wf[p] = wpu[5 + p];
        wg[p] = wpu[10 + p];
        wo[p] = wpu[15 + p];
    }

    unsigned long long hp[5];   // packed h2 pairs
#pragma unroll
    for (int p = 0; p < 5; p++) hp[p] = 0ull;
    float c = 0.f;

    wait_flag(0);

    float4 buf[PF];
#pragma unroll
    for (int s = 0; s < PF; s++) buf[s] = __ldg(&g_xg4[s * 10 + j]);

    for (int ck = 0; ck < NCHUNK; ck++) {
        int lk = ck + 1; if (lk > NCHUNK - 1) lk = NCHUNK - 1;
        wait_flag(lk);                    // covers prefetch into next chunk
        const int t0 = ck * CH;

        for (int u = 0; u < CH / PF; u++) {
#pragma unroll
            for (int s = 0; s < PF; s++) {
                const int t = t0 + u * PF + s;
                float4 g4 = buf[s];
                // prefetch t+PF (clamped; flags guarantee availability)
                int tn = t + PF; if (tn > T_SEQ - 1) tn = T_SEQ - 1;
                buf[s] = __ldg(&g_xg4[tn * 10 + j]);

                unsigned long long ai, af, ag, ao;
                MUL2(ai, wi[0], hp[0]);
                MUL2(af, wf[0], hp[0]);
                MUL2(ag, wg[0], hp[0]);
                MUL2(ao, wo[0], hp[0]);
#pragma unroll
                for (int p = 1; p < 5; p++) {
                    FMA2(ai, wi[p], hp[p], ai);
                    FMA2(af, wf[p], hp[p], af);
                    FMA2(ag, wg[p], hp[p], ag);
                    FMA2(ao, wo[p], hp[p], ao);
                }
                float l0, h0, l1, h1, l2, h2r, l3, h3;
                UPK2(l0, h0, ai);
                UPK2(l1, h1, af);
                UPK2(l2, h2r, ag);
                UPK2(l3, h3, ao);
                float si = g4.x + (l0 + h0);
                float sf = g4.y + (l1 + h1);
                float sg = g4.z + (l2 + h2r);
                float so = g4.w + (l3 + h3);

                float ti = fast_tanh(si);
                float tf = fast_tanh(sf);
                float tg = fast_tanh(sg);
                float to = fast_tanh(so);

                // c = vf*c + vi*vg with vi=0.5(ti+1) etc.
                float aa = fmaf(tf, c, c);
                float bbv = fmaf(ti, tg, tg);
                c = 0.5f * (aa + bbv);
                float tc = fast_tanh(c);
                float h2v = fmaf(to, tc, tc);     // = 2*h

                if (lane < 10) g_h2[t * 10 + lane] = h2v;

                // broadcast h2 and repack pairs for next step
                float hk[10];
#pragma unroll
                for (int k = 0; k < 10; k++)
                    hk[k] = __shfl_sync(0xffffffffu, h2v, k);
#pragma unroll
                for (int p = 0; p < 5; p++)
                    PK2(hp[p], hk[2 * p], hk[2 * p + 1]);
            }
        }
        // publish progress (release)
        __syncwarp();
        __threadfence();
        __syncwarp();
        if (lane == 0) g_prog = t0 + CH;
    }
}

// ---------------- gemm consumer (all other warps) ---------------------------
__device__ void gemm_consumer(const float* __restrict__ W_out,
                              const float* __restrict__ b_out,
                              float* __restrict__ out) {
    const int lane = threadIdx.x & 31;
    const int total = N_TT * N_OT;

    for (;;) {
        int tk;
        if (lane == 0) tk = atomicAdd(&g_ticket, 1);
        tk = __shfl_sync(0xffffffffu, tk, 0);
        if (tk >= total) return;

        const int tt = tk / N_OT;
        const int ot = tk - tt * N_OT;
        const int t0 = tt * GT;
        const int o0 = ot * GO + lane;

        float w[4][10], bb[4];
        bool val[4];
#pragma unroll
        for (int r = 0; r < 4; r++) {
            int o = o0 + 32 * r;
            val[r] = (o < O_DIM);
            bb[r] = val[r] ? __ldg(b_out + o) : 0.f;
#pragma unroll
            for (int k = 0; k < 10; k++)
                w[r][k] = val[r] ? 0.5f * __ldg(W_out + (size_t)o * 10 + k) : 0.f;
        }

        const int need = t0 + GT;
        while (g_prog < need) __nanosleep(256);
        __threadfence();

        float hcur = (lane < 10) ? __ldg(&g_h2[t0 * 10 + lane]) : 0.f;
        for (int t = t0; t < t0 + GT; t++) {
            int tn = t + 1; if (tn > T_SEQ - 1) tn = T_SEQ - 1;
            float hnext = (lane < 10) ? __ldg(&g_h2[tn * 10 + lane]) : 0.f;
            float hk[10];
#pragma unroll
            for (int k = 0; k < 10; k++)
                hk[k] = __shfl_sync(0xffffffffu, hcur, k);
            const size_t rb = (size_t)t * O_DIM;
#pragma unroll
            for (int r = 0; r < 4; r++) {
                if (val[r]) {
                    float acc = bb[r];
#pragma unroll
                    for (int k = 0; k < 10; k++) acc = fmaf(w[r][k], hk[k], acc);
                    out[rb + o0 + 32 * r] = acc;
                }
            }
            hcur = hnext;
        }
    }
}

// ---------------- fused persistent kernel -----------------------------------
__global__ void __launch_bounds__(NTHR, 1)
fused_kernel(const int* __restrict__ x,
             const float* __restrict__ emb,
             const float* __restrict__ w_ih,
             const float* __restrict__ b_ih,
             const float* __restrict__ b_hh,
             const float* __restrict__ W_out,
             const float* __restrict__ b_out,
             float* __restrict__ out) {
    const int b = blockIdx.x;
    const int tid = threadIdx.x;

    // --- dedicated recurrence block: warp 0 recurs, rest of block idles ---
    if (b == NBLK - 1) {
        if (tid < 32) recurrence_warp();
        return;
    }

    // --- embed phase: block b < 128 computes xg for t in [32b, 32b+32) ---
    if (b < NCHUNK) {
        float* xg = (float*)g_xg4;
        for (int i = tid; i < CH * 40; i += NTHR) {
            const int t = b * CH + i / 40;
            const int r = i % 40;
            const float4* e = (const float4*)(emb + (size_t)__ldg(x + t) * E_DIM);
            const float4* wv4 = (const float4*)(w_ih + (size_t)r * E_DIM);
            float a0 = 0.f, a1 = 0.f, a2 = 0.f, a3 = 0.f;
#pragma unroll 8
            for (int q = 0; q < E_DIM / 4; q++) {
                float4 ev = __ldg(e + q);
                float4 wv = __ldg(wv4 + q);
                a0 += ev.x * wv.x;
                a1 += ev.y * wv.y;
                a2 += ev.z * wv.z;
                a3 += ev.w * wv.w;
            }
            float v = (__ldg(b_ih + r) + __ldg(b_hh + r)) + ((a0 + a1) + (a2 + a3));
            const int gate = r / 10;
            const int j = r - gate * 10;
            if (gate != 2) v *= 0.5f;          // sigmoid half-angle fold
            xg[(t * 10 + j) * 4 + gate] = v;
        }
        __syncthreads();
        __threadfence();
        if (tid == 0) g_flag[b] = 1;
    }

    // --- gemm phase: everyone drains tickets ---
    gemm_consumer(W_out, b_out, out);
}

// ---------------- launch ----------------------------------------------------
extern "C" void kernel_launch(void* const* d_in, const int* in_sizes, int n_in,
                              void* d_out, int out_size) {
    const int*   x     = (const int*)d_in[0];
    const float* emb   = (const float*)d_in[1];
    const float* w_ih  = (const float*)d_in[2];
    const float* w_hh  = (const float*)d_in[3];
    const float* b_ih  = (const float*)d_in[4];
    const float* b_hh  = (const float*)d_in[5];
    const float* W_out = (const float*)d_in[6];
    const float* b_out = (const float*)d_in[7];
    float* out = (float*)d_out;

    init_kernel<<<1, 256>>>(w_hh);
    fused_kernel<<<NBLK, NTHR>>>(x, emb, w_ih, b_ih, b_hh, W_out, b_out, out);
}

// round 3
// speedup vs baseline: 1.2142x; 1.0793x over previous
#include <cuda_runtime.h>
#include <cstdint>

#define T_SEQ 4096
#define E_DIM 256
#define O_DIM 50257
#define NCHUNK 128           // 128 chunks of 32 timesteps
#define CH 32
#define GT 64                // gemm t-tile
#define GO 128               // gemm o-tile (per warp: 4 o's x 32 lanes)
#define N_OT ((O_DIM + GO - 1) / GO)   // 393
#define N_TT (T_SEQ / GT)              // 64
#define NBLK 148
#define NTHR 512

// ---------------- device globals (no allocation allowed) --------------------
__device__ float4 g_xg4[T_SEQ * 10];      // [t][j] -> (xi,xf,xg,xo); i/f/o pre-scaled 0.5
__device__ float  g_h2[T_SEQ * 10];       // h2 = 2*h
__device__ volatile int g_flag[NCHUNK];   // embed chunk ready flags
__device__ volatile int g_prog;           // recurrence progress (timesteps done)
__device__ int g_ticket;                  // gemm work ticket

// ---------------- helpers ---------------------------------------------------
__device__ __forceinline__ float fast_tanh(float x) {
    float y;
    asm("tanh.approx.f32 %0, %1;" : "=f"(y) : "f"(x));
    return y;
}

// ---------------- init kernel -----------------------------------------------
__global__ void init_kernel() {
    int i = threadIdx.x;
    if (i < NCHUNK) g_flag[i] = 0;
    if (i == 0) { g_prog = 0; g_ticket = 0; }
}

// ---------------- recurrence block (block NBLK-1) ---------------------------
// warp 0: serial LSTM; warp 1: gmem->smem staging of xg chunks.

struct RecShared {
    float4 xg[2][CH * 10];        // double buffer, 5KB each
    volatile int ready[2];
};

__device__ void staging_warp(RecShared* sh) {
    const int lane = threadIdx.x & 31;
    for (int ck = 0; ck < NCHUNK; ck++) {
        const int b = ck & 1;
        while (sh->ready[b] != 0) __nanosleep(64);       // wait buffer free
        while (g_flag[ck] == 0) __nanosleep(64);         // wait producer
        __threadfence();                                  // acquire
        const float4* src = &g_xg4[ck * CH * 10];
#pragma unroll
        for (int i = 0; i < 10; i++)
            sh->xg[b][lane + 32 * i] = __ldg(src + lane + 32 * i);
        __syncwarp();
        __threadfence_block();
        if (lane == 0) sh->ready[b] = 1;
    }
}

__device__ void recurrence_warp(const float* __restrict__ w_hh, RecShared* sh) {
    const int lane = threadIdx.x;
    const int j = (lane < 10) ? lane : 0;

    // scaled recurrent weights in registers
    // i,f,o gates: x0.25 (sigmoid half-angle fold x h2 fold); g gate: x0.5
    float wi[10], wf[10], wg[10], wo[10];
#pragma unroll
    for (int k = 0; k < 10; k++) {
        wi[k] = w_hh[(0 * 10 + j) * 10 + k] * 0.25f;
        wf[k] = w_hh[(1 * 10 + j) * 10 + k] * 0.25f;
        wg[k] = w_hh[(2 * 10 + j) * 10 + k] * 0.5f;
        wo[k] = w_hh[(3 * 10 + j) * 10 + k] * 0.25f;
    }

    float hk[10];
#pragma unroll
    for (int k = 0; k < 10; k++) hk[k] = 0.f;
    float c = 0.f;

    for (int ck = 0; ck < NCHUNK; ck++) {
        const int b = ck & 1;
        while (sh->ready[b] == 0) __nanosleep(32);
        __threadfence_block();
        const float4* src = sh->xg[b];
        const int t0 = ck * CH;

        float4 cur[4], nxt[4];
#pragma unroll
        for (int s = 0; s < 4; s++) cur[s] = src[s * 10 + j];

        for (int gg = 0; gg < 8; gg++) {
            if (gg < 7) {
#pragma unroll
                for (int s = 0; s < 4; s++)
                    nxt[s] = src[(gg * 4 + 4 + s) * 10 + j];
            }
#pragma unroll
            for (int s = 0; s < 4; s++) {
                const int t = t0 + gg * 4 + s;
                const float4 g4 = cur[s];

                // 8 independent 5-FMA chains
                float ia = fmaf(wi[0], hk[0], g4.x), ib = wi[5] * hk[5];
                float fa = fmaf(wf[0], hk[0], g4.y), fb = wf[5] * hk[5];
                float ga = fmaf(wg[0], hk[0], g4.z), gb = wg[5] * hk[5];
                float oa = fmaf(wo[0], hk[0], g4.w), ob = wo[5] * hk[5];
#pragma unroll
                for (int k = 1; k < 5; k++) {
                    ia = fmaf(wi[k], hk[k], ia);  ib = fmaf(wi[k + 5], hk[k + 5], ib);
                    fa = fmaf(wf[k], hk[k], fa);  fb = fmaf(wf[k + 5], hk[k + 5], fb);
                    ga = fmaf(wg[k], hk[k], ga);  gb = fmaf(wg[k + 5], hk[k + 5], gb);
                    oa = fmaf(wo[k], hk[k], oa);  ob = fmaf(wo[k + 5], hk[k + 5], ob);
                }
                float ti = fast_tanh(ia + ib);
                float tf = fast_tanh(fa + fb);
                float tg = fast_tanh(ga + gb);
                float to = fast_tanh(oa + ob);

                // c = 0.5*((tf*c + c) + (ti*tg + tg))
                float bbv = fmaf(ti, tg, tg);
                float hb  = 0.5f * bbv;
                float aa  = fmaf(tf, c, c);
                c = fmaf(0.5f, aa, hb);
                float tc = fast_tanh(c);
                float h2v = fmaf(to, tc, tc);            // = 2*h

                if (lane < 10) g_h2[t * 10 + lane] = h2v;

#pragma unroll
                for (int k = 0; k < 10; k++)
                    hk[k] = __shfl_sync(0xffffffffu, h2v, k);
            }
#pragma unroll
            for (int s = 0; s < 4; s++) cur[s] = nxt[s];
        }

        // free buffer + publish progress
        __syncwarp();
        if (lane == 0) sh->ready[b] = 0;
        __threadfence();
        if (lane == 0) g_prog = t0 + CH;
    }
}

// ---------------- gemm consumer (all other warps) ---------------------------
__device__ void gemm_consumer(const float* __restrict__ W_out,
                              const float* __restrict__ b_out,
                              float* __restrict__ out) {
    const int lane = threadIdx.x & 31;
    const int total = N_TT * N_OT;

    for (;;) {
        int tk;
        if (lane == 0) tk = atomicAdd(&g_ticket, 1);
        tk = __shfl_sync(0xffffffffu, tk, 0);
        if (tk >= total) return;

        const int tt = tk / N_OT;
        const int ot = tk - tt * N_OT;
        const int t0 = tt * GT;
        const int o0 = ot * GO + lane;

        float w[4][10], bb[4];
        bool val[4];
#pragma unroll
        for (int r = 0; r < 4; r++) {
            int o = o0 + 32 * r;
            val[r] = (o < O_DIM);
            bb[r] = val[r] ? __ldg(b_out + o) : 0.f;
#pragma unroll
            for (int k = 0; k < 10; k++)
                w[r][k] = val[r] ? 0.5f * __ldg(W_out + (size_t)o * 10 + k) : 0.f;
        }

        const int need = t0 + GT;
        while (g_prog < need) __nanosleep(256);
        __threadfence();

        float hcur = (lane < 10) ? __ldg(&g_h2[t0 * 10 + lane]) : 0.f;
        for (int t = t0; t < t0 + GT; t++) {
            int tn = t + 1; if (tn > T_SEQ - 1) tn = T_SEQ - 1;
            float hnext = (lane < 10) ? __ldg(&g_h2[tn * 10 + lane]) : 0.f;
            float hk[10];
#pragma unroll
            for (int k = 0; k < 10; k++)
                hk[k] = __shfl_sync(0xffffffffu, hcur, k);
            const size_t rb = (size_t)t * O_DIM;
#pragma unroll
            for (int r = 0; r < 4; r++) {
                if (val[r]) {
                    float acc = bb[r];
#pragma unroll
                    for (int k = 0; k < 10; k++) acc = fmaf(w[r][k], hk[k], acc);
                    out[rb + o0 + 32 * r] = acc;
                }
            }
            hcur = hnext;
        }
    }
}

// ---------------- fused persistent kernel -----------------------------------
__global__ void __launch_bounds__(NTHR, 1)
fused_kernel(const int* __restrict__ x,
             const float* __restrict__ emb,
             const float* __restrict__ w_ih,
             const float* __restrict__ b_ih,
             const float* __restrict__ b_hh,
             const float* __restrict__ w_hh,
             const float* __restrict__ W_out,
             const float* __restrict__ b_out,
             float* __restrict__ out) {
    const int b = blockIdx.x;
    const int tid = threadIdx.x;

    // --- dedicated recurrence block ---
    if (b == NBLK - 1) {
        __shared__ RecShared sh;
        if (tid == 0) { sh.ready[0] = 0; sh.ready[1] = 0; }
        __syncthreads();
        if (tid < 32) recurrence_warp(w_hh, &sh);
        else if (tid < 64) staging_warp(&sh);
        return;
    }

    // --- embed phase: block b < 128 computes xg for t in [32b, 32b+32) ---
    if (b < NCHUNK) {
        float* xg = (float*)g_xg4;
        for (int i = tid; i < CH * 40; i += NTHR) {
            const int t = b * CH + i / 40;
            const int r = i % 40;
            const float4* e = (const float4*)(emb + (size_t)__ldg(x + t) * E_DIM);
            const float4* wv4 = (const float4*)(w_ih + (size_t)r * E_DIM);
            float a0 = 0.f, a1 = 0.f, a2 = 0.f, a3 = 0.f;
#pragma unroll 8
            for (int q = 0; q < E_DIM / 4; q++) {
                float4 ev = __ldg(e + q);
                float4 wv = __ldg(wv4 + q);
                a0 += ev.x * wv.x;
                a1 += ev.y * wv.y;
                a2 += ev.z * wv.z;
                a3 += ev.w * wv.w;
            }
            float v = (__ldg(b_ih + r) + __ldg(b_hh + r)) + ((a0 + a1) + (a2 + a3));
            const int gate = r / 10;
            const int j = r - gate * 10;
            if (gate != 2) v *= 0.5f;          // sigmoid half-angle fold
            xg[(t * 10 + j) * 4 + gate] = v;
        }
        __syncthreads();
        __threadfence();
        if (tid == 0) g_flag[b] = 1;
    }

    // --- gemm phase: everyone drains tickets ---
    gemm_consumer(W_out, b_out, out);
}

// ---------------- launch ----------------------------------------------------
extern "C" void kernel_launch(void* const* d_in, const int* in_sizes, int n_in,
                              void* d_out, int out_size) {
    const int*   x     = (const int*)d_in[0];
    const float* emb   = (const float*)d_in[1];
    const float* w_ih  = (const float*)d_in[2];
    const float* w_hh  = (const float*)d_in[3];
    const float* b_ih  = (const float*)d_in[4];
    const float* b_hh  = (const float*)d_in[5];
    const float* W_out = (const float*)d_in[6];
    const float* b_out = (const float*)d_in[7];
    float* out = (float*)d_out;

    init_kernel<<<1, 256>>>();
    fused_kernel<<<NBLK, NTHR>>>(x, emb, w_ih, b_ih, b_hh, w_hh, W_out, b_out, out);
}

// round 4
// speedup vs baseline: 1.9773x; 1.6284x over previous
#include <cuda_runtime.h>
#include <cstdint>

#define T_SEQ 4096
#define E_DIM 256
#define O_DIM 50257
#define NCHUNK 128           // 128 chunks of 32 timesteps
#define CH 32
#define GT 64                // gemm t-tile
#define GO 128               // gemm o-tile (per warp: 4 o's x 32 lanes)
#define N_OT ((O_DIM + GO - 1) / GO)   // 393
#define N_TT (T_SEQ / GT)              // 64
#define NBLK 148
#define NTHR 512

// ---------------- device globals (no allocation allowed) --------------------
__device__ float g_xg[T_SEQ * 40];        // [t][d], d = gate*10+unit; i/f/o pre-scaled 0.5
__device__ float g_h2[T_SEQ * 10];        // h2 = 2*h
__device__ volatile int g_flag[NCHUNK];   // embed chunk ready flags
__device__ volatile int g_prog;           // recurrence progress (timesteps done)
__device__ int g_ticket;                  // gemm work ticket

// ---------------- helpers ---------------------------------------------------
__device__ __forceinline__ float fast_tanh(float x) {
    float y;
    asm("tanh.approx.f32 %0, %1;" : "=f"(y) : "f"(x));
    return y;
}

// ---------------- init kernel -----------------------------------------------
__global__ void init_kernel() {
    int i = threadIdx.x;
    if (i < NCHUNK) g_flag[i] = 0;
    if (i == 0) { g_prog = 0; g_ticket = 0; }
}

// ---------------- recurrence block (block NBLK-1) ---------------------------
// warp 0: serial LSTM (work spread over all 32 lanes); warp 1: gmem->smem staging.

struct RecShared {
    float xg[2][CH * 40];         // double buffer, 5KB each
    volatile int ready[2];
};

__device__ void staging_warp(RecShared* sh) {
    const int lane = threadIdx.x & 31;
    for (int ck = 0; ck < NCHUNK; ck++) {
        const int b = ck & 1;
        while (sh->ready[b] != 0) __nanosleep(64);       // wait buffer free
        while (g_flag[ck] == 0) __nanosleep(64);         // wait producer
        __threadfence();                                  // acquire
        const float4* src = (const float4*)&g_xg[ck * CH * 40];
        float4* dst = (float4*)sh->xg[b];
#pragma unroll
        for (int i = 0; i < 10; i++)
            dst[lane + 32 * i] = __ldg(src + lane + 32 * i);
        __syncwarp();
        __threadfence_block();
        if (lane == 0) sh->ready[b] = 1;
    }
}

__device__ void recurrence_warp(const float* __restrict__ w_hh, RecShared* sh) {
    const int lane = threadIdx.x;
    // dot assignments: dA = lane (0..31), dB = 32 + (lane&7) (32..39)
    const int dA = lane;
    const int dB = 32 + (lane & 7);
    // unit owned for the c/h update (lanes 0..9 meaningful)
    const int j = (lane < 10) ? lane : (lane - 10 < 10 ? lane - 10 : lane - 20);
    // source lane for the o-gate value of unit j
    const int srcO = (j < 2) ? (30 + j) : (j - 2);
    const bool oFromA = (j < 2);

    // per-dot scaled weights: gate 2 (g) x0.5, others x0.25
    float wA[10], wB[10];
    const float sA = ((dA / 10) == 2) ? 0.5f : 0.25f;
    const float sB = 0.25f;   // dB in [32,39] -> gate 3 (o)
#pragma unroll
    for (int k = 0; k < 10; k++) {
        wA[k] = w_hh[dA * 10 + k] * sA;
        wB[k] = w_hh[dB * 10 + k] * sB;
    }

    float hk[10];
#pragma unroll
    for (int k = 0; k < 10; k++) hk[k] = 0.f;
    float c = 0.f;

    for (int ck = 0; ck < NCHUNK; ck++) {
        const int b = ck & 1;
        while (sh->ready[b] == 0) __nanosleep(32);
        __threadfence_block();
        const float* src = sh->xg[b];
        const int t0 = ck * CH;

        float xa = src[dA];
        float xb = src[dB];

#pragma unroll 4
        for (int tt = 0; tt < CH; tt++) {
            const int t = t0 + tt;
            // prefetch next step's xg (clamped inside chunk)
            const int tp = (tt < CH - 1) ? tt + 1 : tt;
            float xa_n = src[tp * 40 + dA];
            float xb_n = src[tp * 40 + dB];

            // distributed dots: two 5-FMA chains each
            float aA = fmaf(wA[0], hk[0], xa), bA = wA[5] * hk[5];
            float aB = fmaf(wB[0], hk[0], xb), bB = wB[5] * hk[5];
#pragma unroll
            for (int k = 1; k < 5; k++) {
                aA = fmaf(wA[k], hk[k], aA);  bA = fmaf(wA[k + 5], hk[k + 5], bA);
                aB = fmaf(wB[k], hk[k], aB);  bB = fmaf(wB[k + 5], hk[k + 5], bB);
            }
            const float tA = fast_tanh(aA + bA);
            const float tB = fast_tanh(aB + bB);

            // gather the 4 gate values for unit j
            const float ti = __shfl_sync(0xffffffffu, tA, j);
            const float tf = __shfl_sync(0xffffffffu, tA, 10 + j);
            const float tg = __shfl_sync(0xffffffffu, tA, 20 + j);
            const float vA = __shfl_sync(0xffffffffu, tA, srcO);
            const float vB = __shfl_sync(0xffffffffu, tB, srcO);
            const float to = oFromA ? vA : vB;

            // c = 0.5*((tf*c + c) + (ti*tg + tg)) ; h2 = (to+1)*tanh(c)
            const float bbv = fmaf(ti, tg, tg);
            const float hb  = 0.5f * bbv;
            const float aa  = fmaf(tf, c, c);
            c = fmaf(0.5f, aa, hb);
            const float tc = fast_tanh(c);
            const float h2v = fmaf(to, tc, tc);

            if (lane < 10) g_h2[t * 10 + lane] = h2v;

            // broadcast h2 for next step's dots
#pragma unroll
            for (int k = 0; k < 10; k++)
                hk[k] = __shfl_sync(0xffffffffu, h2v, k);

            xa = xa_n;
            xb = xb_n;
        }

        // free buffer + publish progress (release)
        __syncwarp();
        if (lane == 0) sh->ready[b] = 0;
        __threadfence();
        if (lane == 0) g_prog = t0 + CH;
    }
}

// ---------------- gemm consumer (all other warps) ---------------------------
__device__ void gemm_consumer(const float* __restrict__ W_out,
                              const float* __restrict__ b_out,
                              float* __restrict__ out) {
    const int lane = threadIdx.x & 31;
    const int total = N_TT * N_OT;

    for (;;) {
        int tk;
        if (lane == 0) tk = atomicAdd(&g_ticket, 1);
        tk = __shfl_sync(0xffffffffu, tk, 0);
        if (tk >= total) return;

        const int tt = tk / N_OT;
        const int ot = tk - tt * N_OT;
        const int t0 = tt * GT;
        const int o0 = ot * GO + lane;

        float w[4][10], bb[4];
        bool val[4];
#pragma unroll
        for (int r = 0; r < 4; r++) {
            int o = o0 + 32 * r;
            val[r] = (o < O_DIM);
            bb[r] = val[r] ? __ldg(b_out + o) : 0.f;
#pragma unroll
            for (int k = 0; k < 10; k++)
                w[r][k] = val[r] ? 0.5f * __ldg(W_out + (size_t)o * 10 + k) : 0.f;
        }

        const int need = t0 + GT;
        while (g_prog < need) __nanosleep(256);
        __threadfence();

        float hcur = (lane < 10) ? __ldg(&g_h2[t0 * 10 + lane]) : 0.f;
        for (int t = t0; t < t0 + GT; t++) {
            int tn = t + 1; if (tn > T_SEQ - 1) tn = T_SEQ - 1;
            float hnext = (lane < 10) ? __ldg(&g_h2[tn * 10 + lane]) : 0.f;
            float hk[10];
#pragma unroll
            for (int k = 0; k < 10; k++)
                hk[k] = __shfl_sync(0xffffffffu, hcur, k);
            const size_t rb = (size_t)t * O_DIM;
#pragma unroll
            for (int r = 0; r < 4; r++) {
                if (val[r]) {
                    float acc = bb[r];
#pragma unroll
                    for (int k = 0; k < 10; k++) acc = fmaf(w[r][k], hk[k], acc);
                    out[rb + o0 + 32 * r] = acc;
                }
            }
            hcur = hnext;
        }
    }
}

// ---------------- fused persistent kernel -----------------------------------
__global__ void __launch_bounds__(NTHR, 1)
fused_kernel(const int* __restrict__ x,
             const float* __restrict__ emb,
             const float* __restrict__ w_ih,
             const float* __restrict__ b_ih,
             const float* __restrict__ b_hh,
             const float* __restrict__ w_hh,
             const float* __restrict__ W_out,
             const float* __restrict__ b_out,
             float* __restrict__ out) {
    const int b = blockIdx.x;
    const int tid = threadIdx.x;

    // --- dedicated recurrence block ---
    if (b == NBLK - 1) {
        __shared__ RecShared sh;
        if (tid == 0) { sh.ready[0] = 0; sh.ready[1] = 0; }
        __syncthreads();
        if (tid < 32) recurrence_warp(w_hh, &sh);
        else if (tid < 64) staging_warp(&sh);
        return;
    }

    // --- embed phase: block b < 128 computes xg for t in [32b, 32b+32) ---
    if (b < NCHUNK) {
        for (int i = tid; i < CH * 40; i += NTHR) {
            const int t = b * CH + i / 40;
            const int r = i % 40;
            const float4* e = (const float4*)(emb + (size_t)__ldg(x + t) * E_DIM);
            const float4* wv4 = (const float4*)(w_ih + (size_t)r * E_DIM);
            float a0 = 0.f, a1 = 0.f, a2 = 0.f, a3 = 0.f;
#pragma unroll 8
            for (int q = 0; q < E_DIM / 4; q++) {
                float4 ev = __ldg(e + q);
                float4 wv = __ldg(wv4 + q);
                a0 += ev.x * wv.x;
                a1 += ev.y * wv.y;
                a2 += ev.z * wv.z;
                a3 += ev.w * wv.w;
            }
            float v = (__ldg(b_ih + r) + __ldg(b_hh + r)) + ((a0 + a1) + (a2 + a3));
            if (r / 10 != 2) v *= 0.5f;        // sigmoid half-angle fold
            g_xg[t * 40 + r] = v;
        }
        __syncthreads();
        __threadfence();
        if (tid == 0) g_flag[b] = 1;
    }

    // --- gemm phase: everyone drains tickets ---
    gemm_consumer(W_out, b_out, out);
}

// ---------------- launch ----------------------------------------------------
extern "C" void kernel_launch(void* const* d_in, const int* in_sizes, int n_in,
                              void* d_out, int out_size) {
    const int*   x     = (const int*)d_in[0];
    const float* emb   = (const float*)d_in[1];
    const float* w_ih  = (const float*)d_in[2];
    const float* w_hh  = (const float*)d_in[3];
    const float* b_ih  = (const float*)d_in[4];
    const float* b_hh  = (const float*)d_in[5];
    const float* W_out = (const float*)d_in[6];
    const float* b_out = (const float*)d_in[7];
    float* out = (float*)d_out;

    init_kernel<<<1, 256>>>();
    fused_kernel<<<NBLK, NTHR>>>(x, emb, w_ih, b_ih, b_hh, w_hh, W_out, b_out, out);
}

// round 5
// speedup vs baseline: 2.0494x; 1.0365x over previous
#include <cuda_runtime.h>
#include <cstdint>

#define T_SEQ 4096
#define E_DIM 256
#define O_DIM 50257
#define NCHUNK 128           // 128 chunks of 32 timesteps
#define CH 32
#define GT 64                // gemm t-tile
#define GO 128               // gemm o-tile (per warp: 4 o's x 32 lanes)
#define N_OT ((O_DIM + GO - 1) / GO)   // 393
#define N_TT (T_SEQ / GT)              // 64
#define NBLK 148
#define NTHR 512

// ---------------- device globals (no allocation allowed) --------------------
__device__ float g_xg[T_SEQ * 40];        // [t][d], d = gate*10+unit; i/f/o pre-scaled 0.5
__device__ float g_h2[T_SEQ * 10];        // h2 = 2*h
__device__ volatile int g_flag[NCHUNK];   // embed chunk ready flags
__device__ volatile int g_prog;           // recurrence progress (timesteps done)
__device__ int g_ticket;                  // gemm work ticket

// ---------------- helpers ---------------------------------------------------
__device__ __forceinline__ float fast_tanh(float x) {
    float y;
    asm("tanh.approx.f32 %0, %1;" : "=f"(y) : "f"(x));
    return y;
}

// ---------------- init kernel -----------------------------------------------
__global__ void init_kernel() {
    int i = threadIdx.x;
    if (i < NCHUNK) g_flag[i] = 0;
    if (i == 0) { g_prog = 0; g_ticket = 0; }
}

// ---------------- recurrence block (block NBLK-1) ---------------------------
// warp 0: serial LSTM (work spread over all 32 lanes); warp 1: gmem->smem staging.

struct RecShared {
    float xg[2][CH * 40];         // double buffer, 5KB each
    volatile int ready[2];
};

__device__ void staging_warp(RecShared* sh) {
    const int lane = threadIdx.x & 31;
    for (int ck = 0; ck < NCHUNK; ck++) {
        const int b = ck & 1;
        while (sh->ready[b] != 0) __nanosleep(64);       // wait buffer free
        while (g_flag[ck] == 0) __nanosleep(64);         // wait producer
        __threadfence();                                  // acquire
        const float4* src = (const float4*)&g_xg[ck * CH * 40];
        float4* dst = (float4*)sh->xg[b];
#pragma unroll
        for (int i = 0; i < 10; i++)
            dst[lane + 32 * i] = __ldg(src + lane + 32 * i);
        __syncwarp();
        __threadfence_block();
        if (lane == 0) sh->ready[b] = 1;
    }
}

// 10-dot with 4-way split accumulators: depth = 3 FMA (12cyc) + add tree (8cyc)
__device__ __forceinline__ float dot10(const float* w, const float* hk, float x0) {
    float a = fmaf(w[0], hk[0], x0);
    a = fmaf(w[1], hk[1], a);
    a = fmaf(w[2], hk[2], a);
    float b = w[3] * hk[3];
    b = fmaf(w[4], hk[4], b);
    b = fmaf(w[5], hk[5], b);
    float d = w[6] * hk[6];
    d = fmaf(w[7], hk[7], d);
    d = fmaf(w[8], hk[8], d);
    float e = w[9] * hk[9];
    return (a + b) + (d + e);
}

__device__ void recurrence_warp(const float* __restrict__ w_hh, RecShared* sh) {
    const int lane = threadIdx.x;
    const int j = lane % 10;          // unit owned by this lane (replicated across lanes)
    const int dA = lane;              // dots 0..31: i(0-9), f(10-19), g(20-29), o(30,31 junk)
    const int dB = 30 + j;            // o-dot of unit j -> 'to' is LOCAL, no gather shfl

    // per-dot scaled weights: gate 2 (g) x0.5, others x0.25
    float wA[10], wB[10];
    const float sA = ((dA / 10) == 2) ? 0.5f : 0.25f;
#pragma unroll
    for (int k = 0; k < 10; k++) {
        wA[k] = w_hh[dA * 10 + k] * sA;
        wB[k] = w_hh[dB * 10 + k] * 0.25f;
    }

    float hk[10];
#pragma unroll
    for (int k = 0; k < 10; k++) hk[k] = 0.f;
    float c = 0.f;

    for (int ck = 0; ck < NCHUNK; ck++) {
        const int b = ck & 1;
        while (sh->ready[b] == 0) __nanosleep(32);
        __threadfence_block();
        const float* src = sh->xg[b];
        const int t0 = ck * CH;

        float xa = src[dA];
        float xb = src[dB];

#pragma unroll
        for (int tt = 0; tt < CH; tt++) {
            const int t = t0 + tt;
            // prefetch next step's xg (clamped inside chunk)
            const int tp = (tt < CH - 1) ? tt + 1 : tt;
            const float xa_n = src[tp * 40 + dA];
            const float xb_n = src[tp * 40 + dB];

            const float tA = fast_tanh(dot10(wA, hk, xa));
            const float tB = fast_tanh(dot10(wB, hk, xb));

            // gather i/f/g for unit j (3 independent shfls); o is local (tB)
            const float ti = __shfl_sync(0xffffffffu, tA, j);
            const float tf = __shfl_sync(0xffffffffu, tA, 10 + j);
            const float tg = __shfl_sync(0xffffffffu, tA, 20 + j);
            const float to = tB;

            // c = 0.5*(tf*c + c) + 0.5*(ti*tg + tg) ; h2 = (to+1)*tanh(c)
            const float bbv = fmaf(ti, tg, tg);
            const float hb  = 0.5f * bbv;
            const float aa  = fmaf(tf, c, c);
            c = fmaf(0.5f, aa, hb);
            const float tc = fast_tanh(c);
            const float h2v = fmaf(to, tc, tc);

            if (lane < 10) g_h2[t * 10 + lane] = h2v;

            // broadcast h2 (from lanes 0-9) for next step's dots
#pragma unroll
            for (int k = 0; k < 10; k++)
                hk[k] = __shfl_sync(0xffffffffu, h2v, k);

            xa = xa_n;
            xb = xb_n;
        }

        // free buffer + publish progress (release)
        __syncwarp();
        if (lane == 0) sh->ready[b] = 0;
        __threadfence();
        if (lane == 0) g_prog = t0 + CH;
    }
}

// ---------------- gemm consumer (all other warps) ---------------------------
__device__ void gemm_consumer(const float* __restrict__ W_out,
                              const float* __restrict__ b_out,
                              float* __restrict__ out) {
    const int lane = threadIdx.x & 31;
    const int total = N_TT * N_OT;

    for (;;) {
        int tk;
        if (lane == 0) tk = atomicAdd(&g_ticket, 1);
        tk = __shfl_sync(0xffffffffu, tk, 0);
        if (tk >= total) return;

        const int tt = tk / N_OT;
        const int ot = tk - tt * N_OT;
        const int t0 = tt * GT;
        const int o0 = ot * GO + lane;

        float w[4][10], bb[4];
        bool val[4];
#pragma unroll
        for (int r = 0; r < 4; r++) {
            int o = o0 + 32 * r;
            val[r] = (o < O_DIM);
            bb[r] = val[r] ? __ldg(b_out + o) : 0.f;
#pragma unroll
            for (int k = 0; k < 10; k++)
                w[r][k] = val[r] ? 0.5f * __ldg(W_out + (size_t)o * 10 + k) : 0.f;
        }

        const int need = t0 + GT;
        while (g_prog < need) __nanosleep(256);
        __threadfence();

        float hcur = (lane < 10) ? __ldg(&g_h2[t0 * 10 + lane]) : 0.f;
        for (int t = t0; t < t0 + GT; t++) {
            int tn = t + 1; if (tn > T_SEQ - 1) tn = T_SEQ - 1;
            float hnext = (lane < 10) ? __ldg(&g_h2[tn * 10 + lane]) : 0.f;
            float hk[10];
#pragma unroll
            for (int k = 0; k < 10; k++)
                hk[k] = __shfl_sync(0xffffffffu, hcur, k);
            const size_t rb = (size_t)t * O_DIM;
#pragma unroll
            for (int r = 0; r < 4; r++) {
                if (val[r]) {
                    float acc = bb[r];
#pragma unroll
                    for (int k = 0; k < 10; k++) acc = fmaf(w[r][k], hk[k], acc);
                    out[rb + o0 + 32 * r] = acc;
                }
            }
            hcur = hnext;
        }
    }
}

// ---------------- fused persistent kernel -----------------------------------
__global__ void __launch_bounds__(NTHR, 1)
fused_kernel(const int* __restrict__ x,
             const float* __restrict__ emb,
             const float* __restrict__ w_ih,
             const float* __restrict__ b_ih,
             const float* __restrict__ b_hh,
             const float* __restrict__ w_hh,
             const float* __restrict__ W_out,
             const float* __restrict__ b_out,
             float* __restrict__ out) {
    const int b = blockIdx.x;
    const int tid = threadIdx.x;

    // --- dedicated recurrence block ---
    if (b == NBLK - 1) {
        __shared__ RecShared sh;
        if (tid == 0) { sh.ready[0] = 0; sh.ready[1] = 0; }
        __syncthreads();
        if (tid < 32) recurrence_warp(w_hh, &sh);
        else if (tid < 64) staging_warp(&sh);
        return;
    }

    // --- embed phase: block b < 128 computes xg for t in [32b, 32b+32) ---
    if (b < NCHUNK) {
        for (int i = tid; i < CH * 40; i += NTHR) {
            const int t = b * CH + i / 40;
            const int r = i % 40;
            const float4* e = (const float4*)(emb + (size_t)__ldg(x + t) * E_DIM);
            const float4* wv4 = (const float4*)(w_ih + (size_t)r * E_DIM);
            float a0 = 0.f, a1 = 0.f, a2 = 0.f, a3 = 0.f;
#pragma unroll 8
            for (int q = 0; q < E_DIM / 4; q++) {
                float4 ev = __ldg(e + q);
                float4 wv = __ldg(wv4 + q);
                a0 += ev.x * wv.x;
                a1 += ev.y * wv.y;
                a2 += ev.z * wv.z;
                a3 += ev.w * wv.w;
            }
            float v = (__ldg(b_ih + r) + __ldg(b_hh + r)) + ((a0 + a1) + (a2 + a3));
            if (r / 10 != 2) v *= 0.5f;        // sigmoid half-angle fold
            g_xg[t * 40 + r] = v;
        }
        __syncthreads();
        __threadfence();
        if (tid == 0) g_flag[b] = 1;
    }

    // --- gemm phase: everyone drains tickets ---
    gemm_consumer(W_out, b_out, out);
}

// ---------------- launch ----------------------------------------------------
extern "C" void kernel_launch(void* const* d_in, const int* in_sizes, int n_in,
                              void* d_out, int out_size) {
    const int*   x     = (const int*)d_in[0];
    const float* emb   = (const float*)d_in[1];
    const float* w_ih  = (const float*)d_in[2];
    const float* w_hh  = (const float*)d_in[3];
    const float* b_ih  = (const float*)d_in[4];
    const float* b_hh  = (const float*)d_in[5];
    const float* W_out = (const float*)d_in[6];
    const float* b_out = (const float*)d_in[7];
    float* out = (float*)d_out;

    init_kernel<<<1, 256>>>();
    fused_kernel<<<NBLK, NTHR>>>(x, emb, w_ih, b_ih, b_hh, w_hh, W_out, b_out, out);
}